// round 7
// baseline (speedup 1.0000x reference)
#include <cuda_runtime.h>
#include <cuda_bf16.h>
#include <cstdint>

#define CUT 512
#define IMG_W 4096
#define HW (4096u * 4096u)
#define PLANE (512u * 512u)
#define IMG_STRIDE (3u * 512u * 512u)

// One block = one full 512-px output row (16 warps). All warps gather from the
// SAME two input rows per channel -> 6 contiguous row-segment streams per
// block, maximal DRAM row-buffer locality. 32 regs x 512 thr = 4 blocks/SM =
// 100% theoretical occupancy. Stores evict-first (__stcs): output never re-read.
__global__ __launch_bounds__(512)
void dango_cutouts_kernel(const float* __restrict__ img,
                          const int* __restrict__ sizes,
                          const int* __restrict__ offy,
                          const int* __restrict__ offx,
                          float* __restrict__ out) {
    const int ox = threadIdx.x;     // 0..511
    const int oy = blockIdx.x;      // 0..511
    const int z  = blockIdx.y;      // 0 = overview, 1..12 = inner crops

    int size, ioy, iox;
    if (z == 0) { size = 4096; ioy = 0; iox = 0; }
    else        { size = sizes[z - 1]; ioy = offy[z - 1]; iox = offx[z - 1]; }

    const float s     = (float)size;
    const float offyf = (float)ioy;
    const float offxf = (float)iox;

    // t = (i + 0.5) * s / 512 - 0.5  (pow2 scale: exact)
    float y = offyf + (((float)oy + 0.5f) * s * (1.0f / 512.0f) - 0.5f);
    y = fminf(fmaxf(y, offyf), offyf + s - 1.0f);
    int   y0 = (int)floorf(y);
    float wy = y - (float)y0;
    int   dy = (y0 + 1 <= ioy + size - 1) ? 1 : 0;   // y1 - y0

    float x = offxf + (((float)ox + 0.5f) * s * (1.0f / 512.0f) - 0.5f);
    x = fminf(fmaxf(x, offxf), offxf + s - 1.0f);
    int   x0 = (int)floorf(x);
    float wx = x - (float)x0;
    int   dx = (x0 + 1 <= iox + size - 1) ? 1 : 0;   // x1 - x0

    const unsigned base = (unsigned)y0 * (unsigned)IMG_W + (unsigned)x0;
    const unsigned drow = (unsigned)dy * (unsigned)IMG_W;

    // ---- batch the 12 loads (front-loaded for MLP) ----
    float v[3][4];
    #pragma unroll
    for (int c = 0; c < 3; c++) {
        const float* __restrict__ p = img + (unsigned)c * HW + base;
        v[c][0] = __ldg(p);
        v[c][1] = __ldg(p + dx);
        v[c][2] = __ldg(p + drow);
        v[c][3] = __ldg(p + drow + dx);
    }

    float rgb[3];
    #pragma unroll
    for (int c = 0; c < 3; c++) {
        float top = v[c][0] * (1.0f - wx) + v[c][1] * wx;
        float bot = v[c][2] * (1.0f - wx) + v[c][3] * wx;
        rgb[c] = top * (1.0f - wy) + bot * wy;
    }
    const float gray = 0.2989f * rgb[0] + 0.587f * rgb[1] + 0.114f * rgb[2];

    const unsigned pix = (unsigned)oy * (unsigned)CUT + (unsigned)ox;

    if (z == 0) {
        // One full-resize sample feeds all 4 overview images.
        // flipped(y, x) = full(y, 511-x)
        const unsigned pixf = (unsigned)oy * (unsigned)CUT + (unsigned)(CUT - 1 - ox);
        #pragma unroll
        for (int c = 0; c < 3; c++) {
            __stcs(out + 0u * IMG_STRIDE + (unsigned)c * PLANE + pix,  rgb[c]);
            __stcs(out + 1u * IMG_STRIDE + (unsigned)c * PLANE + pix,  gray);
            __stcs(out + 2u * IMG_STRIDE + (unsigned)c * PLANE + pixf, rgb[c]);
            __stcs(out + 3u * IMG_STRIDE + (unsigned)c * PLANE + pixf, gray);
        }
    } else {
        const unsigned base_o = (unsigned)(3 + z) * IMG_STRIDE;  // output image 4 + (z-1)
        if (z == 1) {
            #pragma unroll
            for (int c = 0; c < 3; c++)
                __stcs(out + base_o + (unsigned)c * PLANE + pix, gray);
        } else {
            #pragma unroll
            for (int c = 0; c < 3; c++)
                __stcs(out + base_o + (unsigned)c * PLANE + pix, rgb[c]);
        }
    }
}

extern "C" void kernel_launch(void* const* d_in, const int* in_sizes, int n_in,
                              void* d_out, int out_size) {
    const float* img   = (const float*)d_in[0];   // (1,3,4096,4096) fp32
    // d_in[1] = t (unused scalar)
    const int*   sizes = (const int*)d_in[2];     // (12,)
    const int*   offy  = (const int*)d_in[3];     // (12,)
    const int*   offx  = (const int*)d_in[4];     // (12,)
    float* out = (float*)d_out;                   // (16,3,512,512) fp32

    dim3 block(512, 1, 1);
    dim3 grid(CUT, 13, 1);  // one block per output row per image-slot
    dango_cutouts_kernel<<<grid, block>>>(img, sizes, offy, offx, out);
}